// round 17
// baseline (speedup 1.0000x reference)
#include <cuda_runtime.h>
#include <cuda_bf16.h>
#include <math.h>

// Problem constants
#define SEQ   2048
#define NB    2
#define NH    16
#define HDIM  64
#define DM    1024
#define BHT   (NB*NH)        // 32 batch*heads
#define MROWS (NB*SEQ)       // 4096

// bf16 GEMM tile config: 128x128 block tile, 4 warps of 64x64, BK=32, 3-stage
#define BM 128
#define BN 128
#define BKH 32
#define LDAH 40
#define LDBH 40
#define GSTAGE_A (BM*LDAH)
#define GSTAGE_B (BN*LDBH)

// Flash attention (all-bf16 tiles, stride 72 elements = 144B rows)
#define FQ  72

typedef __nv_bfloat16 bf;
typedef __nv_bfloat162 bf2;

// ---------------- scratch (device globals: allocation-free) ----------------
__device__ unsigned short g_xb [(size_t)MROWS*DM];
__device__ unsigned short g_wt7[7][DM*DM];                  // [N][K] bf16
__device__ unsigned short g_gwt[2*DM*DM];                   // gate_w transposed
__device__ unsigned short g_hb16[6][BHT*SEQ*HDIM];          // bf16 proj outputs
__device__ float g_unused[BHT*SEQ*HDIM];                    // dummy fp32 sink (unwritten)
__device__ unsigned short g_fwdb  [(size_t)MROWS*DM];
__device__ unsigned short g_bwdb  [(size_t)MROWS*DM];
__device__ unsigned short g_fusedb[(size_t)MROWS*DM];
__device__ unsigned short g_gpreb[(size_t)MROWS*DM];        // bf16 gate pre-activations
__device__ float g_out2[(size_t)MROWS*DM];

// ---------------- helpers ----------------
__device__ __forceinline__ void cpa8(unsigned dst, const void* src) {
    asm volatile("cp.async.ca.shared.global [%0], [%1], 8;" :: "r"(dst), "l"(src));
}
__device__ __forceinline__ void cp16(unsigned dst, const void* src) {
    asm volatile("cp.async.cg.shared.global [%0], [%1], 16;" :: "r"(dst), "l"(src));
}
__device__ __forceinline__ void cp_commit() { asm volatile("cp.async.commit_group;"); }
template<int N> __device__ __forceinline__ void cp_wait() {
    asm volatile("cp.async.wait_group %0;" :: "n"(N));
}
__device__ __forceinline__ void ldm_x4(unsigned* r, unsigned addr) {
    asm volatile("ldmatrix.sync.aligned.m8n8.x4.shared.b16 {%0,%1,%2,%3}, [%4];"
        : "=r"(r[0]), "=r"(r[1]), "=r"(r[2]), "=r"(r[3]) : "r"(addr));
}
__device__ __forceinline__ void ldm_x4t(unsigned* r, unsigned addr) {
    asm volatile("ldmatrix.sync.aligned.m8n8.x4.trans.shared.b16 {%0,%1,%2,%3}, [%4];"
        : "=r"(r[0]), "=r"(r[1]), "=r"(r[2]), "=r"(r[3]) : "r"(addr));
}
__device__ __forceinline__ float ex2_(float x) {
    float y; asm("ex2.approx.f32 %0, %1;" : "=f"(y) : "f"(x)); return y;
}

// bf16 m16n8k16, fp32 accumulate
__device__ __forceinline__ void mma16(float* c, const unsigned* a, unsigned b0, unsigned b1) {
    asm volatile(
        "mma.sync.aligned.m16n8k16.row.col.f32.bf16.bf16.f32 "
        "{%0,%1,%2,%3}, {%4,%5,%6,%7}, {%8,%9}, {%0,%1,%2,%3};"
        : "+f"(c[0]), "+f"(c[1]), "+f"(c[2]), "+f"(c[3])
        : "r"(a[0]), "r"(a[1]), "r"(a[2]), "r"(a[3]), "r"(b0), "r"(b1));
}

__device__ __forceinline__ float sigmoidf_(float x) { return 1.f / (1.f + __expf(-x)); }

// ---------------- conversion kernels ----------------
__global__ void cvt_x_kernel(const float4* __restrict__ x, bf2* __restrict__ xb) {
    int i = blockIdx.x * 256 + threadIdx.x;
    float4 t = x[i];
    xb[2 * i]     = __floats2bfloat162_rn(t.x, t.y);
    xb[2 * i + 1] = __floats2bfloat162_rn(t.z, t.w);
}

struct TW { const float* W[7]; unsigned short* Wt[7]; };

__global__ void transpose_w7(TW t) {
    __shared__ float sm[32][33];
    const float* W = t.W[blockIdx.z];
    bf* out = (bf*)t.Wt[blockIdx.z];
    const int n0 = blockIdx.x * 32, k0 = blockIdx.y * 32;
    const int tx = threadIdx.x, ty = threadIdx.y;
#pragma unroll
    for (int j = 0; j < 32; j += 8)
        sm[ty + j][tx] = W[(size_t)(k0 + ty + j) * DM + n0 + tx];
    __syncthreads();
#pragma unroll
    for (int j = 0; j < 32; j += 8)
        out[(size_t)(n0 + ty + j) * DM + k0 + tx] = __float2bfloat16(sm[tx][ty + j]);
}

__global__ void transpose_w_kernel(const float* __restrict__ W, unsigned short* __restrict__ Wt,
                                   int K, int N) {
    __shared__ float t[32][33];
    const int n0 = blockIdx.x * 32, k0 = blockIdx.y * 32;
    const int tx = threadIdx.x, ty = threadIdx.y;
#pragma unroll
    for (int j = 0; j < 32; j += 8)
        t[ty + j][tx] = W[(size_t)(k0 + ty + j) * N + n0 + tx];
    __syncthreads();
    bf* out = (bf*)Wt;
#pragma unroll
    for (int j = 0; j < 32; j += 8)
        out[(size_t)(n0 + ty + j) * K + k0 + tx] = __float2bfloat16(t[tx][ty + j]);
}

// ---------------- bf16 GEMM (3-stage cp.async, ldmatrix feeding) ----------------
struct GB {
    const unsigned short *A0, *A1, *Bt;
    const float* bias;
    float* Cf;
    unsigned short* Cb1;       // MODE 1: if set, write bf16 here instead of fp32 Cf
    int N, K, KA0, maskF, maskB;
    const unsigned short* Bt6[6]; const float* b6[6];
    float* o6[6]; unsigned short* ob6[6];
};

template<int MODE>
__device__ __forceinline__ void issue_bf(
    const GB& g, const unsigned short* Ap, const unsigned short* Btp,
    unsigned short* As, unsigned short* Bs, int m0, int n0, int ks, int tid)
{
    unsigned aB = (unsigned)__cvta_generic_to_shared(As);
    unsigned bB = (unsigned)__cvta_generic_to_shared(Bs);
#pragma unroll
    for (int i = 0; i < 8; i++) {
        int e = i * 128 + tid, mm = e >> 3, c4 = (e & 7) * 4;
        const unsigned short* src;
        if (MODE == 0) src = Ap + (size_t)(m0 + mm) * g.K + ks + c4;
        else { int gk = ks + c4;
            src = (gk < g.KA0) ? g.A0 + (size_t)(m0 + mm) * g.KA0 + gk
                               : g.A1 + (size_t)(m0 + mm) * g.KA0 + (gk - g.KA0); }
        cpa8(aB + (unsigned)(mm * LDAH + c4) * 2u, src);
    }
#pragma unroll
    for (int i = 0; i < 8; i++) {
        int e = i * 128 + tid, nn = e >> 3, c4 = (e & 7) * 4;
        cpa8(bB + (unsigned)(nn * LDBH + c4) * 2u, Btp + (size_t)(n0 + nn) * g.K + ks + c4);
    }
}

template<int MODE>
__global__ void __launch_bounds__(128, 2) gemm_bf(GB g)
{
    extern __shared__ unsigned short gsm[];
    const unsigned gsmU = (unsigned)__cvta_generic_to_shared(gsm);

    const int nb = blockIdx.x, mb = blockIdx.y, z = blockIdx.z;
    const int m0 = mb * BM, n0 = nb * BN;

    const unsigned short *Ap, *Btp; const float* bias; float* Cf; unsigned short* Cb;
    if (MODE == 0) { Ap = g.A0; Btp = g.Bt6[z]; bias = g.b6[z]; Cf = g.o6[z]; Cb = g.ob6[z]; }
    else           { Ap = g.A0; Btp = g.Bt; bias = g.bias; Cf = g.Cf; Cb = g.Cb1; }

    const int tid = threadIdx.x, lane = tid & 31, warp = tid >> 5;
    const int wm = (warp & 1) * 64, wn = (warp >> 1) * 64;
    const int qrow = lane >> 2, qcol = lane & 3;
    const int la15 = lane & 15, la16 = lane >> 4;
    const int bg = lane >> 3, br = lane & 7;

    const unsigned aOff = (unsigned)((wm + la15) * LDAH + la16 * 8);
    const unsigned bOff = (unsigned)((wn + ((bg >> 1) * 8) + br) * LDBH + (bg & 1) * 8);

    float acc[4][8][4] = {};
    const int nIter = g.K / BKH;

    issue_bf<MODE>(g, Ap, Btp, gsm, gsm + 3 * GSTAGE_A, m0, n0, 0, tid);
    cp_commit();
    issue_bf<MODE>(g, Ap, Btp, gsm + GSTAGE_A, gsm + 3 * GSTAGE_A + GSTAGE_B, m0, n0, BKH, tid);
    cp_commit();

    int bi = 0;
    for (int it = 0; it < nIter; ++it) {
        if (it + 1 < nIter) cp_wait<1>(); else cp_wait<0>();
        __syncthreads();
        if (it + 2 < nIter) {
            int wb = bi + 2; if (wb >= 3) wb -= 3;
            issue_bf<MODE>(g, Ap, Btp, gsm + wb * GSTAGE_A,
                           gsm + 3 * GSTAGE_A + wb * GSTAGE_B, m0, n0, (it + 2) * BKH, tid);
            cp_commit();
        }
        const unsigned aSt = gsmU + (unsigned)(bi * GSTAGE_A) * 2u;
        const unsigned bSt = gsmU + (unsigned)(3 * GSTAGE_A + bi * GSTAGE_B) * 2u;
#pragma unroll
        for (int kk = 0; kk < BKH; kk += 16) {
            unsigned a[4][4];
#pragma unroll
            for (int mf = 0; mf < 4; mf++)
                ldm_x4(a[mf], aSt + (aOff + (unsigned)(mf * 16 * LDAH + kk)) * 2u);
            unsigned bfr[4][4];
#pragma unroll
            for (int nfp = 0; nfp < 4; nfp++)
                ldm_x4(bfr[nfp], bSt + (bOff + (unsigned)(nfp * 16 * LDBH + kk)) * 2u);
#pragma unroll
            for (int nf = 0; nf < 8; nf++) {
                unsigned b0 = bfr[nf >> 1][(nf & 1) * 2];
                unsigned b1 = bfr[nf >> 1][(nf & 1) * 2 + 1];
#pragma unroll
                for (int mf = 0; mf < 4; mf++)
                    mma16(acc[mf][nf], a[mf], b0, b1);
            }
        }
        if (++bi == 3) bi = 0;
    }

    const bool doF = (MODE != 0) || ((g.maskF >> z) & 1);
    const bool doB = (MODE == 0) && ((g.maskB >> z) & 1);
#pragma unroll
    for (int mf = 0; mf < 4; mf++)
#pragma unroll
    for (int nf = 0; nf < 8; nf++)
#pragma unroll
    for (int t2 = 0; t2 < 2; t2++) {
        int r   = m0 + wm + mf * 16 + qrow + t2 * 8;
        int col = n0 + wn + nf * 8 + qcol * 2;
        float v0 = acc[mf][nf][t2 * 2] + bias[col];
        float v1 = acc[mf][nf][t2 * 2 + 1] + bias[col + 1];
        if (MODE == 0) {
            int b = r >> 11, s = r & (SEQ - 1), h = col >> 6, hd = col & 63;
            size_t off = ((size_t)(b * NH + h) * SEQ + s) * HDIM + hd;
            if (doF) *reinterpret_cast<float2*>(&Cf[off]) = make_float2(v0, v1);
            if (doB) *reinterpret_cast<bf2*>((bf*)Cb + off) = __floats2bfloat162_rn(v0, v1);
        } else if (Cb) {
            *reinterpret_cast<bf2*>((bf*)Cb + (size_t)r * g.N + col) =
                __floats2bfloat162_rn(v0, v1);
        } else {
            *reinterpret_cast<float2*>(&Cf[(size_t)r * g.N + col]) = make_float2(v0, v1);
        }
    }
}

// ---------------- fused causal flash attention (all-bf16, LPT dispatch, 2-sync) ------
// SMEM: Qs@0 (18432) | Ks[2]@18432 (2x9216) | Vs[2]@36864 (2x9216) | Ps@55296 (18432)
__global__ void __launch_bounds__(256, 2) flash_fwd_kernel(
    const unsigned short* __restrict__ Qg, const unsigned short* __restrict__ Kg,
    const unsigned short* __restrict__ Vg, unsigned short* __restrict__ fwdb)
{
    extern __shared__ char sm_[];
    bf* Qs  = (bf*)sm_;
    bf* Psb = (bf*)(sm_ + 55296);
    const unsigned sbase = (unsigned)__cvta_generic_to_shared(sm_);

    // LPT: dispatch largest causal blocks first
    const int m0 = (SEQ / 128 - 1 - blockIdx.x) * 128;
    const int bh = blockIdx.y;
    const bf* Qp = (const bf*)Qg + (size_t)bh * SEQ * HDIM;
    const bf* Kp = (const bf*)Kg + (size_t)bh * SEQ * HDIM;
    const bf* Vp = (const bf*)Vg + (size_t)bh * SEQ * HDIM;

    const int tid = threadIdx.x, lane = tid & 31, warp = tid >> 5;
    const int wm = warp * 16;
    const int qrow = lane >> 2, qcol = lane & 3;
    const int bg = lane >> 3, br = lane & 7;
    const int la15 = lane & 15, la16 = lane >> 4;
    const unsigned kOff = (unsigned)((((bg >> 1) * 8) + br) * FQ + (bg & 1) * 8);
    const unsigned pOff = (unsigned)((wm + la15) * FQ + la16 * 8);
    const unsigned vLane = (unsigned)((((lane >> 3) & 1) * 8 + (lane & 7)) * FQ + (lane >> 4) * 8);

    auto issue_kv = [&](int kt2, int buf) {
        unsigned kb = sbase + 18432u + (unsigned)buf * 9216u;
        unsigned vb = sbase + 36864u + (unsigned)buf * 9216u;
        const int nk = kt2 * 64;
#pragma unroll
        for (int i = 0; i < 2; i++) {
            int e = i * 256 + tid, r = e >> 3, c8 = (e & 7) * 8;
            cp16(kb + (unsigned)(r * FQ + c8) * 2u, Kp + (size_t)(nk + r) * HDIM + c8);
            cp16(vb + (unsigned)(r * FQ + c8) * 2u, Vp + (size_t)(nk + r) * HDIM + c8);
        }
    };

    issue_kv(0, 0);
    cp_commit();

#pragma unroll
    for (int i = 0; i < 4; i++) {
        int e = i * 256 + tid, r = e >> 3, c8 = (e & 7) * 8;
        *reinterpret_cast<uint4*>(Qs + r * FQ + c8) =
            *reinterpret_cast<const uint4*>(Qp + (size_t)(m0 + r) * HDIM + c8);
    }
    __syncthreads();

    // lift Q fragments, fold scale 0.125*log2(e) into Q (log2-domain scores)
    const bf qsc = __float2bfloat16(0.180336881f);
    const bf2 qsc2 = __halves2bfloat162(qsc, qsc);
    unsigned qf[4][4];
#pragma unroll
    for (int ks = 0; ks < 4; ks++) {
        int r = wm + qrow, c = 16 * ks + 2 * qcol;
        qf[ks][0] = *(const unsigned*)(Qs + r * FQ + c);
        qf[ks][1] = *(const unsigned*)(Qs + (r + 8) * FQ + c);
        qf[ks][2] = *(const unsigned*)(Qs + r * FQ + c + 8);
        qf[ks][3] = *(const unsigned*)(Qs + (r + 8) * FQ + c + 8);
#pragma unroll
        for (int j = 0; j < 4; j++) {
            bf2 v = *reinterpret_cast<bf2*>(&qf[ks][j]);
            v = __hmul2(v, qsc2);
            qf[ks][j] = *reinterpret_cast<unsigned*>(&v);
        }
    }

    float o[8][4] = {};
    float mrow[2] = {-1e30f, -1e30f};
    float lrow[2] = {0.f, 0.f};

    const int ntiles = m0 / 64 + 2;
    for (int kt = 0; kt < ntiles; kt++) {
        const int n0k = kt * 64;
        const int buf = kt & 1;
        cp_wait<0>();
        __syncthreads();                           // A: KV[buf] ready; PV(kt-1) retired
        if (kt + 1 < ntiles) {
            issue_kv(kt + 1, buf ^ 1);
            cp_commit();
        }

        const unsigned kSt = sbase + 18432u + (unsigned)buf * 9216u;
        const unsigned vSt = sbase + 36864u + (unsigned)buf * 9216u;

        // S = Q @ K^T (log2-domain)
        float s[8][4] = {};
#pragma unroll
        for (int ks = 0; ks < 4; ks++) {
            unsigned bfr[4][4];
#pragma unroll
            for (int nfp = 0; nfp < 4; nfp++)
                ldm_x4(bfr[nfp], kSt + (kOff + (unsigned)(nfp * 16 * FQ + 16 * ks)) * 2u);
#pragma unroll
            for (int nf = 0; nf < 8; nf++) {
                unsigned b0 = bfr[nf >> 1][(nf & 1) * 2];
                unsigned b1 = bfr[nf >> 1][(nf & 1) * 2 + 1];
                mma16(s[nf], qf[ks], b0, b1);
            }
        }

        // online softmax (base-2)
        const bool domask = (n0k + 63 > m0);
#pragma unroll
        for (int t2 = 0; t2 < 2; t2++) {
            const int row = m0 + wm + qrow + t2 * 8;
            float tmax = -1e30f;
            if (domask) {
#pragma unroll
                for (int nf = 0; nf < 8; nf++)
#pragma unroll
                for (int j = 0; j < 2; j++) {
                    int key = n0k + nf * 8 + qcol * 2 + j;
                    if (key > row) s[nf][t2 * 2 + j] = -1e30f;
                    tmax = fmaxf(tmax, s[nf][t2 * 2 + j]);
                }
            } else {
#pragma unroll
                for (int nf = 0; nf < 8; nf++)
#pragma unroll
                for (int j = 0; j < 2; j++)
                    tmax = fmaxf(tmax, s[nf][t2 * 2 + j]);
            }
            tmax = fmaxf(tmax, __shfl_xor_sync(0xffffffffu, tmax, 1));
            tmax = fmaxf(tmax, __shfl_xor_sync(0xffffffffu, tmax, 2));
            float mnew = fmaxf(mrow[t2], tmax);
            float alpha = ex2_(mrow[t2] - mnew);
            float psum = 0.f;
#pragma unroll
            for (int nf = 0; nf < 8; nf++)
#pragma unroll
            for (int j = 0; j < 2; j++) {
                float p = ex2_(s[nf][t2 * 2 + j] - mnew);
                s[nf][t2 * 2 + j] = p;
                psum += p;
            }
            psum += __shfl_xor_sync(0xffffffffu, psum, 1);
            psum += __shfl_xor_sync(0xffffffffu, psum, 2);
            lrow[t2] = lrow[t2] * alpha + psum;
            mrow[t2] = mnew;
#pragma unroll
            for (int nf = 0; nf < 8; nf++) {
                o[nf][t2 * 2]     *= alpha;
                o[nf][t2 * 2 + 1] *= alpha;
            }
        }

        // write P (bf16) to smem
#pragma unroll
        for (int t2 = 0; t2 < 2; t2++) {
            int r = wm + qrow + t2 * 8;
#pragma unroll
            for (int nf = 0; nf < 8; nf++) {
                *reinterpret_cast<bf2*>(Psb + r * FQ + nf * 8 + qcol * 2) =
                    __floats2bfloat162_rn(s[nf][t2 * 2], s[nf][t2 * 2 + 1]);
            }
        }
        __syncthreads();                           // B: P ready

        // O += P @ V (bf16: ldmatrix A + ldmatrix.trans B)
        const unsigned pSt = sbase + 55296u;
#pragma unroll
        for (int ks4 = 0; ks4 < 4; ks4++) {
            unsigned a[4];
            ldm_x4(a, pSt + (pOff + (unsigned)(ks4 * 16)) * 2u);
#pragma unroll
            for (int np = 0; np < 4; np++) {
                unsigned v4[4];
                ldm_x4t(v4, vSt + (vLane + (unsigned)(ks4 * 16 * FQ + np * 16)) * 2u);
                mma16(o[np * 2],     a, v4[0], v4[1]);
                mma16(o[np * 2 + 1], a, v4[2], v4[3]);
            }
        }
    }

    const int b = bh >> 4, h = bh & 15;
#pragma unroll
    for (int t2 = 0; t2 < 2; t2++) {
        int srow = m0 + wm + qrow + t2 * 8;
        float inv = 1.f / lrow[t2];
        size_t base = ((size_t)(b * SEQ + srow)) * DM + h * HDIM;
#pragma unroll
        for (int nf = 0; nf < 8; nf++) {
            *reinterpret_cast<bf2*>((bf*)fwdb + base + nf * 8 + qcol * 2) =
                __floats2bfloat162_rn(o[nf][t2 * 2] * inv, o[nf][t2 * 2 + 1] * inv);
        }
    }
}

// ---------------- tiled window-32 backward attention (bf16 inputs) ----------------
__global__ void __launch_bounds__(256) bwd_attn_kernel(
    const unsigned short* __restrict__ Qb, const unsigned short* __restrict__ Kb,
    const unsigned short* __restrict__ Vb, unsigned short* __restrict__ bwdb)
{
    extern __shared__ float bsm[];
    float* Ks = bsm;              // 96 x 65
    float* Vs = bsm + 96 * 65;    // 96 x 65
    __shared__ float qsh[8][66];

    const int m0 = blockIdx.x * 64;
    const int bh = blockIdx.y;
    const bf* Qp = (const bf*)Qb + (size_t)bh * SEQ * HDIM;
    const bf* Kp = (const bf*)Kb + (size_t)bh * SEQ * HDIM;
    const bf* Vp = (const bf*)Vb + (size_t)bh * SEQ * HDIM;
    const int b = bh >> 4, h = bh & 15;

    const int tid = threadIdx.x, wid = tid >> 5, lane = tid & 31;
    const int nrows = min(96, SEQ - 1 - m0);

    for (int i = tid; i < nrows * 8; i += 256) {
        int row = i >> 3, c8 = (i & 7) * 8;
        uint4 tk = *reinterpret_cast<const uint4*>(Kp + (size_t)(m0 + 1 + row) * HDIM + c8);
        uint4 tv = *reinterpret_cast<const uint4*>(Vp + (size_t)(m0 + 1 + row) * HDIM + c8);
        const bf2* pk = reinterpret_cast<const bf2*>(&tk);
        const bf2* pv = reinterpret_cast<const bf2*>(&tv);
        float* dk = Ks + row * 65 + c8;
        float* dv = Vs + row * 65 + c8;
#pragma unroll
        for (int j = 0; j < 4; j++) {
            float2 fk = __bfloat1622float2(pk[j]);
            float2 fv = __bfloat1622float2(pv[j]);
            dk[2 * j] = fk.x; dk[2 * j + 1] = fk.y;
            dv[2 * j] = fv.x; dv[2 * j + 1] = fv.y;
        }
    }
    __syncthreads();

#pragma unroll
    for (int t = 0; t < 8; t++) {
        const int m = m0 + wid * 8 + t;
        int w = SEQ - 1 - m; if (w > 32) w = 32;
        if (w <= 0) continue;

        __syncwarp();
        qsh[wid][lane]      = __bfloat162float(Qp[m * HDIM + lane]);
        qsh[wid][lane + 32] = __bfloat162float(Qp[m * HDIM + lane + 32]);
        __syncwarp();

        float sc = -1e30f;
        if (lane < w) {
            const float* kr = Ks + (m - m0 + lane) * 65;
            float a = 0.f;
#pragma unroll
            for (int d = 0; d < HDIM; d++) a += qsh[wid][d] * kr[d];
            sc = a * 0.125f;
        }
        float mx = sc;
#pragma unroll
        for (int o = 16; o > 0; o >>= 1) mx = fmaxf(mx, __shfl_xor_sync(0xffffffffu, mx, o));
        float e = __expf(sc - mx);
        float sum = e;
#pragma unroll
        for (int o = 16; o > 0; o >>= 1) sum += __shfl_xor_sync(0xffffffffu, sum, o);
        float p = e / sum;

        float o0 = 0.f, o1 = 0.f;
        for (int kk = 0; kk < w; kk++) {
            float pk = __shfl_sync(0xffffffffu, p, kk);
            const float* vr = Vs + (m - m0 + kk) * 65;
            o0 += pk * vr[lane];
            o1 += pk * vr[lane + 32];
        }
        bf* outp = (bf*)bwdb + ((size_t)(b * SEQ + m)) * DM + h * HDIM;
        outp[lane] = __float2bfloat16(o0);
        outp[lane + 32] = __float2bfloat16(o1);
    }
}

// mean of Vb over all S for the all-masked last row (bf16 input)
__global__ void vb_mean_kernel(const unsigned short* __restrict__ Vb,
                               unsigned short* __restrict__ bwdb) {
    __shared__ float part[4][64];
    const int bh = blockIdx.x, tid = threadIdx.x;
    const int col = tid & 63, grp = tid >> 6;
    const bf* Vp = (const bf*)Vb + (size_t)bh * SEQ * HDIM;
    float s = 0.f;
    for (int r = grp; r < SEQ; r += 4) s += __bfloat162float(Vp[(size_t)r * HDIM + col]);
    part[grp][col] = s;
    __syncthreads();
    if (tid < 64) {
        float m = (part[0][tid] + part[1][tid] + part[2][tid] + part[3][tid]) * (1.f / SEQ);
        int b = bh >> 4, h = bh & 15;
        ((bf*)bwdb)[((size_t)(b * SEQ + SEQ - 1)) * DM + h * HDIM + tid] = __float2bfloat16(m);
    }
}

// ---------------- gate LN + sigmoid + fusion (bf16 everything) ----------------
__global__ void gate_fuse_kernel(const unsigned short* __restrict__ gpreb,
                                 const unsigned short* __restrict__ fwdb,
                                 const unsigned short* __restrict__ bwdb,
                                 const float* __restrict__ gg, const float* __restrict__ gb,
                                 const float* __restrict__ bstr, unsigned short* __restrict__ fusedb) {
    const int r = blockIdx.x, tid = threadIdx.x;
    const bf* rowp = (const bf*)gpreb + (size_t)r * DM;
    __shared__ float red[256];
    float v[4]; float s = 0.f, ss = 0.f;
#pragma unroll
    for (int i = 0; i < 4; i++) {
        v[i] = __bfloat162float(rowp[tid + i * 256]);
        s += v[i]; ss += v[i] * v[i];
    }
    red[tid] = s; __syncthreads();
    for (int o = 128; o > 0; o >>= 1) { if (tid < o) red[tid] += red[tid + o]; __syncthreads(); }
    float mean = red[0] * (1.f / DM); __syncthreads();
    red[tid] = ss; __syncthreads();
    for (int o = 128; o > 0; o >>= 1) { if (tid < o) red[tid] += red[tid + o]; __syncthreads(); }
    float var = red[0] * (1.f / DM) - mean * mean;
    float rstd = rsqrtf(var + 1e-5f);
    float strength = 0.3f * sigmoidf_(bstr[0]);
#pragma unroll
    for (int i = 0; i < 4; i++) {
        int j = tid + i * 256;
        float g = sigmoidf_((v[i] - mean) * rstd * gg[j] + gb[j]);
        size_t o = (size_t)r * DM + j;
        float fw = __bfloat162float(((const bf*)fwdb)[o]);
        float bw = __bfloat162float(((const bf*)bwdb)[o]);
        ((bf*)fusedb)[o] = __float2bfloat16(fw + strength * g * bw);
    }
}

// ---------------- final residual + LayerNorm ----------------
__global__ void final_ln_kernel(const float* __restrict__ x, const float* __restrict__ o2,
                                const float* __restrict__ lg, const float* __restrict__ lb,
                                float* __restrict__ out) {
    const int r = blockIdx.x, tid = threadIdx.x;
    __shared__ float red[256];
    float v[4]; float s = 0.f, ss = 0.f;
#pragma unroll
    for (int i = 0; i < 4; i++) {
        size_t o = (size_t)r * DM + tid + i * 256;
        v[i] = x[o] + o2[o];
        s += v[i]; ss += v[i] * v[i];
    }
    red[tid] = s; __syncthreads();
    for (int o = 128; o > 0; o >>= 1) { if (tid < o) red[tid] += red[tid + o]; __syncthreads(); }
    float mean = red[0] * (1.f / DM); __syncthreads();
    red[tid] = ss; __syncthreads();
    for (int o = 128; o > 0; o >>= 1) { if (tid < o) red[tid] += red[tid + o]; __syncthreads(); }
    float var = red[0] * (1.f / DM) - mean * mean;
    float rstd = rsqrtf(var + 1e-5f);
#pragma unroll
    for (int i = 0; i < 4; i++) {
        int j = tid + i * 256;
        size_t o = (size_t)r * DM + j;
        out[o] = (v[i] - mean) * rstd * lg[j] + lb[j];
    }
}

// ---------------- launch ----------------
extern "C" void kernel_launch(void* const* d_in, const int* in_sizes, int n_in,
                              void* d_out, int out_size) {
    const float* x      = (const float*)d_in[0];
    const float* fq_w   = (const float*)d_in[1];
    const float* fq_b   = (const float*)d_in[2];
    const float* fk_w   = (const float*)d_in[3];
    const float* fk_b   = (const float*)d_in[4];
    const float* fv_w   = (const float*)d_in[5];
    const float* fv_b   = (const float*)d_in[6];
    const float* bq_w   = (const float*)d_in[7];
    const float* bq_b   = (const float*)d_in[8];
    const float* bk_w   = (const float*)d_in[9];
    const float* bk_b   = (const float*)d_in[10];
    const float* bv_w   = (const float*)d_in[11];
    const float* bv_b   = (const float*)d_in[12];
    const float* gate_w = (const float*)d_in[13];
    const float* gate_b = (const float*)d_in[14];
    const float* gln_g  = (const float*)d_in[15];
    const float* gln_b  = (const float*)d_in[16];
    const float* bstr   = (const float*)d_in[17];
    const float* out_w  = (const float*)d_in[18];
    const float* out_b  = (const float*)d_in[19];
    const float* ln_g   = (const float*)d_in[20];
    const float* ln_b   = (const float*)d_in[21];

    unsigned short *xb, *gwt, *fwdb, *bwdb, *fusedb, *gpreb, *wt7, *hb16;
    float *unused, *out2;
    cudaGetSymbolAddress((void**)&xb,     g_xb);
    cudaGetSymbolAddress((void**)&wt7,    g_wt7);
    cudaGetSymbolAddress((void**)&gwt,    g_gwt);
    cudaGetSymbolAddress((void**)&hb16,   g_hb16);
    cudaGetSymbolAddress((void**)&unused, g_unused);
    cudaGetSymbolAddress((void**)&fwdb,   g_fwdb);
    cudaGetSymbolAddress((void**)&bwdb,   g_bwdb);
    cudaGetSymbolAddress((void**)&fusedb, g_fusedb);
    cudaGetSymbolAddress((void**)&gpreb,  g_gpreb);
    cudaGetSymbolAddress((void**)&out2,   g_out2);

    const size_t span = (size_t)BHT * SEQ * HDIM;
    const int flashSmem = 73728;
    const int gemmSmem  = 3 * (GSTAGE_A + GSTAGE_B) * 2;   // 61440
    const int bwdSmem   = 2 * 96 * 65 * 4;                 // 49920
    cudaFuncSetAttribute(flash_fwd_kernel,
                         cudaFuncAttributeMaxDynamicSharedMemorySize, flashSmem);
    cudaFuncSetAttribute(gemm_bf<0>,
                         cudaFuncAttributeMaxDynamicSharedMemorySize, gemmSmem);
    cudaFuncSetAttribute(gemm_bf<1>,
                         cudaFuncAttributeMaxDynamicSharedMemorySize, gemmSmem);
    cudaFuncSetAttribute(bwd_attn_kernel,
                         cudaFuncAttributeMaxDynamicSharedMemorySize, bwdSmem);

    // conversions
    cvt_x_kernel<<<(MROWS * DM / 4) / 256, 256>>>((const float4*)x, (bf2*)xb);
    {
        TW t;
        const float* W[7] = {fq_w, fk_w, fv_w, bq_w, bk_w, bv_w, out_w};
        for (int i = 0; i < 7; i++) { t.W[i] = W[i]; t.Wt[i] = wt7 + (size_t)i * DM * DM; }
        transpose_w7<<<dim3(DM / 32, DM / 32, 7), dim3(32, 8)>>>(t);
        transpose_w_kernel<<<dim3(DM / 32, 2 * DM / 32), dim3(32, 8)>>>(gate_w, gwt, 2 * DM, DM);
    }

    // 6 fused projections: all outputs bf16 only
    {
        GB a = {};
        a.A0 = xb; a.K = DM; a.N = DM; a.KA0 = DM;
        a.maskF = 0; a.maskB = 0b111111;
        const float* Bb[6] = {fq_b, fk_b, fv_b, bq_b, bk_b, bv_b};
        for (int i = 0; i < 6; i++) {
            a.Bt6[i] = wt7 + (size_t)i * DM * DM;
            a.b6[i] = Bb[i];
            a.o6[i] = unused;
            a.ob6[i] = hb16 + (size_t)i * span;
        }
        gemm_bf<0><<<dim3(DM / BN, MROWS / BM, 6), 128, gemmSmem>>>(a);
    }

    // flash attention (all bf16, LPT dispatch)
    flash_fwd_kernel<<<dim3(SEQ / 128, BHT), 256, flashSmem>>>(
        hb16, hb16 + span, hb16 + 2 * span, fwdb);

    // window backward attention + last-row mean (bf16 in)
    bwd_attn_kernel<<<dim3(SEQ / 64, BHT), 256, bwdSmem>>>(
        hb16 + 3 * span, hb16 + 4 * span, hb16 + 5 * span, bwdb);
    vb_mean_kernel<<<BHT, 256>>>(hb16 + 5 * span, bwdb);

    // gate gemm (bf16 output)
    {
        GB a = {};
        a.A0 = fwdb; a.A1 = bwdb; a.Bt = gwt; a.bias = gate_b;
        a.Cf = nullptr; a.Cb1 = gpreb;
        a.N = DM; a.K = 2 * DM; a.KA0 = DM;
        gemm_bf<1><<<dim3(DM / BN, MROWS / BM, 1), 128, gemmSmem>>>(a);
    }
    gate_fuse_kernel<<<MROWS, 256>>>(gpreb, fwdb, bwdb, gln_g, gln_b, bstr, fusedb);

    // output projection (fp32 output for final LN)
    {
        GB a = {};
        a.A0 = fusedb; a.A1 = fusedb; a.Bt = wt7 + (size_t)6 * DM * DM;
        a.bias = out_b; a.Cf = out2; a.Cb1 = nullptr;
        a.N = DM; a.K = DM; a.KA0 = DM;
        gemm_bf<1><<<dim3(DM / BN, MROWS / BM, 1), 128, gemmSmem>>>(a);
    }
    final_ln_kernel<<<MROWS, 256>>>(x, out2, ln_g, ln_b, (float*)d_out);
}